// round 10
// baseline (speedup 1.0000x reference)
#include <cuda_runtime.h>
#include <cuda_fp16.h>
#include <cstdint>

// Problem dims
#define BB    128
#define TT    512
#define DIN   256
#define DH    512
#define G4    2048        // 4*DH
#define DOUT  256
#define RCTA  128         // 8 batch groups x 16 col groups
#define GRPSZ 16

// ---------------- static device scratch ----------------
__device__ __half g_x_h[(size_t)BB * TT * DIN];       // x fp16, [m=t*128+b][k]
__device__ __half g_wx [(size_t)G4 * DIN];            // w_x2h permuted, [p][k]
__device__ __half g_wh [(size_t)G4 * DH];             // w_h2h permuted, [p][k]
__device__ float  g_gbias[G4];                        // permuted biases
__device__ __half g_xg [(size_t)BB * TT * G4];        // xg fp16, [m][p]
__device__ __half g_hbuf[2][BB * DH];                 // double-buffered h (fp16, L2)
__device__ float  g_hlast[BB * DH];                   // final h fp32
__device__ unsigned g_wflags[RCTA * 8];               // per-(CTA,warp) release counters

// permuted gate column: p = cg*128 + w*16 + q*4 + u
//   cg = p>>7, w = (p>>4)&7 (warp), q = (p>>2)&3 (gate), u = p&3 (unit)
// original col = q*512 + (hidden unit = cg*32 + w*4 + u)
__device__ __forceinline__ int gate_col(int p) {
    return ((p >> 2) & 3) * DH + (p >> 7) * 32 + (((p >> 4) & 7) << 2) + (p & 3);
}

__device__ __forceinline__ void mma16816(float& d0, float& d1, float& d2, float& d3,
                                         unsigned a0, unsigned a1, unsigned a2, unsigned a3,
                                         unsigned b0, unsigned b1) {
    asm volatile(
        "mma.sync.aligned.m16n8k16.row.col.f32.f16.f16.f32 "
        "{%0,%1,%2,%3}, {%4,%5,%6,%7}, {%8,%9}, {%0,%1,%2,%3};"
        : "+f"(d0), "+f"(d1), "+f"(d2), "+f"(d3)
        : "r"(a0), "r"(a1), "r"(a2), "r"(a3), "r"(b0), "r"(b1));
}

__device__ __forceinline__ void ldsm_x4(unsigned& a0, unsigned& a1, unsigned& a2, unsigned& a3,
                                        uint32_t addr) {
    asm volatile("ldmatrix.sync.aligned.m8n8.x4.shared.b16 {%0,%1,%2,%3}, [%4];"
                 : "=r"(a0), "=r"(a1), "=r"(a2), "=r"(a3) : "r"(addr));
}

__device__ __forceinline__ uint32_t smem_u32(const void* p) {
    uint32_t a;
    asm("{ .reg .u64 t; cvta.to.shared.u64 t, %1; cvt.u32.u64 %0, t; }" : "=r"(a) : "l"(p));
    return a;
}

__device__ __forceinline__ void stg_cg_u16(__half* p, __half v) {
    unsigned short s = __half_as_ushort(v);
    asm volatile("st.global.cg.u16 [%0], %1;" :: "l"(p), "h"(s) : "memory");
}

// release-increment: orders THIS lane's prior stores before the add (RMW
// release sequence => an acquire read of the final value syncs with all lanes)
__device__ __forceinline__ void red_rel_add1(unsigned* p) {
    asm volatile("red.release.gpu.global.add.u32 [%0], %1;" :: "l"(p), "r"(1u) : "memory");
}
__device__ __forceinline__ unsigned ld_acq(const unsigned* p) {
    unsigned v;
    asm volatile("ld.acquire.gpu.global.u32 %0, [%1];" : "=r"(v) : "l"(p) : "memory");
    return v;
}

__device__ __forceinline__ float sigm(float x) { return 1.0f / (1.0f + __expf(-x)); }
__device__ __forceinline__ float tanh_a(float x) {
    x = fminf(fmaxf(x, -15.f), 15.f);
    float e = __expf(2.f * x);
    return (e - 1.f) / (e + 1.f);
}
__device__ __forceinline__ float lstm_cell(float zi, float zf, float zg, float zo, float& c) {
    float i = sigm(zi), f = sigm(zf), gg = tanh_a(zg), o = sigm(zo);
    c = fmaf(c, f, i * gg);
    return o * tanh_a(c);
}

// ---------------- prep kernels ----------------
__global__ void prep_x_kernel(const float* __restrict__ x) {
    size_t idx = (size_t)blockIdx.x * 256 + threadIdx.x;
    int k = idx & 255;
    int m = (int)(idx >> 8);
    int t = m >> 7, b = m & 127;
    g_x_h[idx] = __float2half_rn(x[((size_t)b * TT + t) * DIN + k]);
}

__global__ void prep_w_kernel(const float* __restrict__ w_x2h, const float* __restrict__ b_x2h,
                              const float* __restrict__ w_h2h, const float* __restrict__ b_h2h) {
    int idx = blockIdx.x * 256 + threadIdx.x;   // 1,048,576 = 2048*512
    {
        int p = idx >> 9, k = idx & 511;
        g_wh[idx] = __float2half_rn(w_h2h[(size_t)k * G4 + gate_col(p)]);
    }
    if (idx < G4 * DIN) {
        int p = idx >> 8, k = idx & 255;
        g_wx[idx] = __float2half_rn(w_x2h[(size_t)k * G4 + gate_col(p)]);
    }
    if (idx < G4) {
        int gc = gate_col(idx);
        g_gbias[idx] = b_x2h[gc] + b_h2h[gc];
    }
    if (idx < RCTA * 8) g_wflags[idx] = 0;
}

// ---------------- GEMM1: xg = x @ wx + bias (fp16 out) ----------------
#define G1_SMEM ((128 * 264 + 64 * 264) * 2)
__global__ __launch_bounds__(256, 1) void gemm1_kernel() {
    extern __shared__ __half sm[];
    __half* x_sm = sm;                 // 128 x 264
    __half* w_sm = sm + 128 * 264;     // 64  x 264
    const int tid = threadIdx.x;
    const int m0 = blockIdx.y * 128, n0 = blockIdx.x * 64;

    const uint4* xs = (const uint4*)g_x_h;
    #pragma unroll 4
    for (int i = tid; i < 4096; i += 256) {
        int r = i >> 5, k8 = (i & 31) << 3;
        *(uint4*)&x_sm[r * 264 + k8] = xs[(size_t)(m0 + r) * 32 + (i & 31)];
    }
    const uint4* ws = (const uint4*)g_wx;
    #pragma unroll 4
    for (int i = tid; i < 2048; i += 256) {
        int c = i >> 5, k8 = (i & 31) << 3;
        *(uint4*)&w_sm[c * 264 + k8] = ws[(size_t)(n0 + c) * 32 + (i & 31)];
    }
    __syncthreads();

    const int w = tid >> 5, lane = tid & 31, g = lane >> 2, q = lane & 3;
    const int r0 = 16 * w + g;
    float acc[8][4];
    #pragma unroll
    for (int nt = 0; nt < 8; nt++) { acc[nt][0] = acc[nt][1] = acc[nt][2] = acc[nt][3] = 0.f; }

    #pragma unroll 4
    for (int kt = 0; kt < 16; kt++) {
        int k0 = kt * 16 + 2 * q;
        unsigned a0 = *(const unsigned*)&x_sm[r0 * 264 + k0];
        unsigned a1 = *(const unsigned*)&x_sm[(r0 + 8) * 264 + k0];
        unsigned a2 = *(const unsigned*)&x_sm[r0 * 264 + k0 + 8];
        unsigned a3 = *(const unsigned*)&x_sm[(r0 + 8) * 264 + k0 + 8];
        #pragma unroll
        for (int nt = 0; nt < 8; nt++) {
            unsigned b0 = *(const unsigned*)&w_sm[(8 * nt + g) * 264 + k0];
            unsigned b1 = *(const unsigned*)&w_sm[(8 * nt + g) * 264 + k0 + 8];
            mma16816(acc[nt][0], acc[nt][1], acc[nt][2], acc[nt][3], a0, a1, a2, a3, b0, b1);
        }
    }
    #pragma unroll
    for (int nt = 0; nt < 8; nt++) {
        int p = n0 + 8 * nt + 2 * q;
        float2 gb = *(const float2*)&g_gbias[p];
        *(__half2*)&g_xg[(size_t)(m0 + r0) * G4 + p] =
            __floats2half2_rn(acc[nt][0] + gb.x, acc[nt][1] + gb.y);
        *(__half2*)&g_xg[(size_t)(m0 + r0 + 8) * G4 + p] =
            __floats2half2_rn(acc[nt][2] + gb.x, acc[nt][3] + gb.y);
    }
}

// ---------------- persistent recurrent kernel ----------------
// 128 CTAs = 8 batch groups x 16 col groups. Weights register-resident.
// Publish: per-LANE red.release increments of per-(CTA,warp) counters —
// no fences, no publish barrier. Consume: ld.acquire poll until 32*t.
// h_sm double-buffered; single pre-MMA __syncthreads per step.
__global__ __launch_bounds__(256, 1) void rec_kernel() {
    __shared__ __half h_sm[2][16 * 520];   // A tile double buffer

    const int tid = threadIdx.x;
    const int j = blockIdx.x;
    const int bg = j >> 4, cg = j & 15;
    const int w = tid >> 5, lane = tid & 31;
    const int g = lane >> 2, tq = lane & 3;
    const int b = tq >> 1;

    // -------- one-time: B fragments -> registers (128 regs) --------
    unsigned breg[128];
    #pragma unroll
    for (int nt = 0; nt < 2; nt++) {
        const __half* wrow = g_wh + (size_t)(cg * 128 + w * 16 + nt * 8 + g) * DH + 2 * tq;
        #pragma unroll
        for (int kt = 0; kt < 32; kt++) {
            breg[nt * 64 + kt * 2]     = *(const unsigned*)(wrow + kt * 16);
            breg[nt * 64 + kt * 2 + 1] = *(const unsigned*)(wrow + kt * 16 + 8);
        }
    }

    // ldmatrix per-lane base within one h_sm buffer
    const uint32_t hbase0 = smem_u32(&h_sm[0][0]);
    const int grp = lane >> 3;
    const uint32_t arow = (uint32_t)((((grp & 1) * 8 + (lane & 7)) * 520
                                     + (grp >> 1) * 8) * 2);
    // poll target: lanes 0-7 -> producer 2w warps 0-7; lanes 8-15 -> 2w+1
    unsigned* myflag = g_wflags + ((bg * 16 + 2 * w + (lane >> 3)) * 8 + (lane & 7));
    unsigned* pubflag = g_wflags + (j * 8 + w);

    float c0 = 0.f, c1 = 0.f;      // cell state: 2 rows x 1 unit per thread

    for (int t = 0; t < TT; t++) {
        // xg prefetch (fp16), in flight during the wait
        const __half* xrow0 = g_xg + (size_t)(t * BB + bg * 16 + g) * G4
                              + cg * 128 + w * 16 + 2 * tq;
        const __half* xrow1 = xrow0 + (size_t)8 * G4;
        __half2 x00 = __ldg((const __half2*)xrow0);
        __half2 x01 = __ldg((const __half2*)(xrow0 + 8));
        __half2 x10 = __ldg((const __half2*)xrow1);
        __half2 x11 = __ldg((const __half2*)(xrow1 + 8));

        float acc[2][4];
        acc[0][0] = acc[0][1] = acc[0][2] = acc[0][3] = 0.f;
        acc[1][0] = acc[1][1] = acc[1][2] = acc[1][3] = 0.f;

        if (t > 0) {
            const int s = t & 1;
            // acquire-poll: 16 producer-warp counters must reach 32*t
            if (lane < 16) {
                const unsigned want = 32u * (unsigned)t;
                while (ld_acq(myflag) < want) { }
            }
            __syncwarp();

            // load producers 2w,2w+1 chunks (2KB) into h_sm[s]
            const uint4* hsrc = (const uint4*)(g_hbuf[s]);
            const int r = lane >> 1, hh = lane & 1;
            #pragma unroll
            for (int ci = 0; ci < 2; ci++) {
                int c = 2 * w + ci;
                #pragma unroll
                for (int jj = 0; jj < 2; jj++) {
                    uint4 v = __ldcg(hsrc + (size_t)(bg * 16 + r) * 64 + c * 4 + hh * 2 + jj);
                    *(uint4*)&h_sm[s][r * 520 + c * 32 + (hh * 2 + jj) * 8] = v;
                }
            }
            __syncthreads();   // all 16 chunks staged (sole per-step barrier)

            // gates += h @ W : 32 kt x 2 HMMA, A via ldmatrix, B in regs
            const uint32_t abase = hbase0 + (uint32_t)s * (16 * 520 * 2) + arow;
            #pragma unroll
            for (int kt = 0; kt < 32; kt++) {
                unsigned a0, a1, a2, a3;
                ldsm_x4(a0, a1, a2, a3, abase + kt * 32);
                mma16816(acc[0][0], acc[0][1], acc[0][2], acc[0][3],
                         a0, a1, a2, a3, breg[kt * 2], breg[kt * 2 + 1]);
                mma16816(acc[1][0], acc[1][1], acc[1][2], acc[1][3],
                         a0, a1, a2, a3, breg[64 + kt * 2], breg[64 + kt * 2 + 1]);
            }
        }

        // add xg
        {
            float2 f;
            f = __half22float2(x00); acc[0][0] += f.x; acc[0][1] += f.y;
            f = __half22float2(x01); acc[1][0] += f.x; acc[1][1] += f.y;
            f = __half22float2(x10); acc[0][2] += f.x; acc[0][3] += f.y;
            f = __half22float2(x11); acc[1][2] += f.x; acc[1][3] += f.y;
        }

        // gate exchange: pair (tq, tq^2); keep e=b slot, send e=1-b slot
        float r00 = __shfl_xor_sync(0xffffffffu, acc[0][1 - b], 2);
        float r01 = __shfl_xor_sync(0xffffffffu, acc[0][3 - b], 2);
        float r10 = __shfl_xor_sync(0xffffffffu, acc[1][1 - b], 2);
        float r11 = __shfl_xor_sync(0xffffffffu, acc[1][3 - b], 2);
        float o00 = acc[0][b],     o01 = acc[0][2 + b];
        float o10 = acc[1][b],     o11 = acc[1][2 + b];

        float zi0 = b ? r00 : o00,  zf0 = b ? o00 : r00;
        float zg0 = b ? r10 : o10,  zo0 = b ? o10 : r10;
        float zi1 = b ? r01 : o01,  zf1 = b ? o01 : r01;
        float zg1 = b ? r11 : o11,  zo1 = b ? o11 : r11;

        float h0 = lstm_cell(zi0, zf0, zg0, zo0, c0);
        float h1 = lstm_cell(zi1, zf1, zg1, zo1, c1);

        const int U = cg * 32 + w * 4 + (((tq & 1) << 1) | b);
        const int row0 = bg * 16 + g, row1 = row0 + 8;

        if (t < TT - 1) {
            __half* hd = g_hbuf[(t + 1) & 1];
            stg_cg_u16(hd + (size_t)row0 * DH + U, __float2half_rn(h0));
            stg_cg_u16(hd + (size_t)row1 * DH + U, __float2half_rn(h1));
            red_rel_add1(pubflag);     // per-lane release: publishes THIS lane's h
        } else {
            g_hlast[(size_t)row0 * DH + U] = h0;
            g_hlast[(size_t)row1 * DH + U] = h1;
        }
    }
}

// ---------------- final FC ----------------
__global__ void fc_kernel(const float* __restrict__ w_fc, const float* __restrict__ b_fc,
                          float* __restrict__ out) {
    __shared__ float hs[DH];
    int bb = blockIdx.x, o = threadIdx.x;
    for (int i = o; i < DH; i += 256) hs[i] = g_hlast[bb * DH + i];
    __syncthreads();
    float acc = b_fc[o];
    #pragma unroll 8
    for (int k = 0; k < DH; k++) acc = fmaf(hs[k], w_fc[(size_t)k * DOUT + o], acc);
    out[bb * DOUT + o] = acc;
}

// ---------------- launch ----------------
extern "C" void kernel_launch(void* const* d_in, const int* in_sizes, int n_in,
                              void* d_out, int out_size) {
    (void)in_sizes; (void)n_in; (void)out_size;
    const float* x     = (const float*)d_in[0];
    const float* w_x2h = (const float*)d_in[1];
    const float* b_x2h = (const float*)d_in[2];
    const float* w_h2h = (const float*)d_in[3];
    const float* b_h2h = (const float*)d_in[4];
    const float* w_fc  = (const float*)d_in[5];
    const float* b_fc  = (const float*)d_in[6];
    float* out = (float*)d_out;

    cudaFuncSetAttribute(gemm1_kernel, cudaFuncAttributeMaxDynamicSharedMemorySize, G1_SMEM);

    prep_x_kernel<<<65536, 256>>>(x);
    prep_w_kernel<<<4096, 256>>>(w_x2h, b_x2h, w_h2h, b_h2h);
    gemm1_kernel<<<dim3(32, 512), 256, G1_SMEM>>>();
    rec_kernel<<<RCTA, 256>>>();
    fc_kernel<<<BB, 256>>>(w_fc, b_fc, out);
}

// round 11
// speedup vs baseline: 1.2592x; 1.2592x over previous
#include <cuda_runtime.h>
#include <cuda_fp16.h>
#include <cstdint>

// Problem dims
#define BB    128
#define TT    512
#define DIN   256
#define DH    512
#define G4    2048        // 4*DH
#define DOUT  256
#define RCTA  128         // 8 batch groups x 16 col groups

// ---------------- static device scratch ----------------
__device__ __half g_wx [(size_t)G4 * DIN];            // w_x2h permuted, [p][k] (1MB, L2)
__device__ __half g_wh [(size_t)G4 * DH];             // w_h2h permuted, [p][k]
__device__ float  g_gbias[G4];                        // permuted biases
__device__ __half g_xg [(size_t)BB * TT * G4];        // xg fp16, [m][p]
__device__ __half g_hbuf[2][BB * DH];                 // double-buffered h (fp16, L2)
__device__ float  g_hlast[BB * DH];                   // final h fp32
__device__ int    g_wflags[RCTA * 8];                 // per-(CTA,warp) flags

// permuted gate column: p = cg*128 + w*16 + q*4 + u
__device__ __forceinline__ int gate_col(int p) {
    return ((p >> 2) & 3) * DH + (p >> 7) * 32 + (((p >> 4) & 7) << 2) + (p & 3);
}

__device__ __forceinline__ void mma16816(float& d0, float& d1, float& d2, float& d3,
                                         unsigned a0, unsigned a1, unsigned a2, unsigned a3,
                                         unsigned b0, unsigned b1) {
    asm volatile(
        "mma.sync.aligned.m16n8k16.row.col.f32.f16.f16.f32 "
        "{%0,%1,%2,%3}, {%4,%5,%6,%7}, {%8,%9}, {%0,%1,%2,%3};"
        : "+f"(d0), "+f"(d1), "+f"(d2), "+f"(d3)
        : "r"(a0), "r"(a1), "r"(a2), "r"(a3), "r"(b0), "r"(b1));
}

__device__ __forceinline__ void ldsm_x4(unsigned& a0, unsigned& a1, unsigned& a2, unsigned& a3,
                                        uint32_t addr) {
    asm volatile("ldmatrix.sync.aligned.m8n8.x4.shared.b16 {%0,%1,%2,%3}, [%4];"
                 : "=r"(a0), "=r"(a1), "=r"(a2), "=r"(a3) : "r"(addr));
}

__device__ __forceinline__ uint32_t smem_u32(const void* p) {
    uint32_t a;
    asm("{ .reg .u64 t; cvta.to.shared.u64 t, %1; cvt.u32.u64 %0, t; }" : "=r"(a) : "l"(p));
    return a;
}

__device__ __forceinline__ void stg_cg_u16(__half* p, __half v) {
    unsigned short s = __half_as_ushort(v);
    asm volatile("st.global.cg.u16 [%0], %1;" :: "l"(p), "h"(s) : "memory");
}

__device__ __forceinline__ float sigm(float x) { return 1.0f / (1.0f + __expf(-x)); }
__device__ __forceinline__ float tanh_a(float x) {
    x = fminf(fmaxf(x, -15.f), 15.f);
    float e = __expf(2.f * x);
    return (e - 1.f) / (e + 1.f);
}
__device__ __forceinline__ float lstm_cell(float zi, float zf, float zg, float zo, float& c) {
    float i = sigm(zi), f = sigm(zf), gg = tanh_a(zg), o = sigm(zo);
    c = fmaf(c, f, i * gg);
    return o * tanh_a(c);
}

// ---------------- prep: weights/biases/flags ----------------
__global__ void prep_w_kernel(const float* __restrict__ w_x2h, const float* __restrict__ b_x2h,
                              const float* __restrict__ w_h2h, const float* __restrict__ b_h2h) {
    int idx = blockIdx.x * 256 + threadIdx.x;   // 1,048,576 = 2048*512
    {
        int p = idx >> 9, k = idx & 511;
        g_wh[idx] = __float2half_rn(w_h2h[(size_t)k * G4 + gate_col(p)]);
    }
    if (idx < G4 * DIN) {
        int p = idx >> 8, k = idx & 255;
        g_wx[idx] = __float2half_rn(w_x2h[(size_t)k * G4 + gate_col(p)]);
    }
    if (idx < G4) {
        int gc = gate_col(idx);
        g_gbias[idx] = b_x2h[gc] + b_h2h[gc];
    }
    if (idx < RCTA * 8) g_wflags[idx] = 0;
}

// ---------------- GEMM1 v2: one block per m-tile (t), fused x convert ----------------
// grid 512 (t), block 256. x tile resident in smem; loop 32 n-slabs of 64 cols
// with register-prefetch double-buffered w_sm (g_wx is 1MB -> L2-resident).
#define G1_SMEM ((128 * 264 + 2 * 64 * 264) * 2)
__global__ __launch_bounds__(256, 1) void gemm1_kernel(const float* __restrict__ x) {
    extern __shared__ __half sm[];
    __half* x_sm = sm;                       // 128 x 264 (K=256 + pad)
    __half* w_sm = sm + 128 * 264;           // 2 x (64 x 264)
    const int tid = threadIdx.x;
    const int t = blockIdx.x;
    const int m0 = t * 128;

    // fused load+convert: row b <- x[b][t][:]  (fp32, contiguous 256)
    #pragma unroll 8
    for (int ii = 0; ii < 32; ii++) {
        int i = tid + ii * 256;              // 8192 float4 total
        int r = i >> 6, f4 = i & 63;
        float4 v = *(const float4*)(x + ((size_t)r * TT + t) * DIN + f4 * 4);
        __half2 h0 = __floats2half2_rn(v.x, v.y);
        __half2 h1 = __floats2half2_rn(v.z, v.w);
        *(__half2*)&x_sm[r * 264 + f4 * 4]     = h0;
        *(__half2*)&x_sm[r * 264 + f4 * 4 + 2] = h1;
    }

    const int w = tid >> 5, lane = tid & 31, g = lane >> 2, q = lane & 3;
    const int r0 = 16 * w + g;
    const int grp = lane >> 3;
    const uint32_t xbase = smem_u32(x_sm);
    const uint32_t abase = xbase + (uint32_t)(((16 * w + (grp & 1) * 8 + (lane & 7)) * 264
                                               + (grp >> 1) * 8) * 2);

    // preload w tile 0 into regs
    uint4 wr[8];
    const uint4* ws = (const uint4*)g_wx;
    #pragma unroll
    for (int ii = 0; ii < 8; ii++) {
        int i = tid + ii * 256;              // c = i>>5, k8 = (i&31)<<3
        wr[ii] = ws[i];                      // tile 0: rows 0..63
    }
    {
        #pragma unroll
        for (int ii = 0; ii < 8; ii++) {
            int i = tid + ii * 256;
            *(uint4*)&w_sm[(i >> 5) * 264 + ((i & 31) << 3)] = wr[ii];
        }
    }
    __syncthreads();

    for (int nt64 = 0; nt64 < 32; nt64++) {
        const int cur = nt64 & 1;
        const __half* wc = w_sm + cur * (64 * 264);
        const int n0 = nt64 * 64;

        if (nt64 < 31) {                     // prefetch next tile into regs
            const uint4* wsn = ws + (size_t)(n0 + 64) * 32;
            #pragma unroll
            for (int ii = 0; ii < 8; ii++) {
                int i = tid + ii * 256;
                wr[ii] = wsn[i];
            }
        }

        float acc[8][4];
        #pragma unroll
        for (int nt = 0; nt < 8; nt++) { acc[nt][0] = acc[nt][1] = acc[nt][2] = acc[nt][3] = 0.f; }

        #pragma unroll 4
        for (int kt = 0; kt < 16; kt++) {
            int k0 = kt * 16 + 2 * q;
            unsigned a0, a1, a2, a3;
            ldsm_x4(a0, a1, a2, a3, abase + kt * 32);
            #pragma unroll
            for (int nt = 0; nt < 8; nt++) {
                unsigned b0 = *(const unsigned*)&wc[(8 * nt + g) * 264 + k0];
                unsigned b1 = *(const unsigned*)&wc[(8 * nt + g) * 264 + k0 + 8];
                mma16816(acc[nt][0], acc[nt][1], acc[nt][2], acc[nt][3], a0, a1, a2, a3, b0, b1);
            }
        }

        #pragma unroll
        for (int nt = 0; nt < 8; nt++) {
            int p = n0 + 8 * nt + 2 * q;
            float2 gb = *(const float2*)&g_gbias[p];
            *(__half2*)&g_xg[(size_t)(m0 + r0) * G4 + p] =
                __floats2half2_rn(acc[nt][0] + gb.x, acc[nt][1] + gb.y);
            *(__half2*)&g_xg[(size_t)(m0 + r0 + 8) * G4 + p] =
                __floats2half2_rn(acc[nt][2] + gb.x, acc[nt][3] + gb.y);
        }

        if (nt64 < 31) {                     // stage next tile (other buffer)
            __half* wn = w_sm + (cur ^ 1) * (64 * 264);
            #pragma unroll
            for (int ii = 0; ii < 8; ii++) {
                int i = tid + ii * 256;
                *(uint4*)&wn[(i >> 5) * 264 + ((i & 31) << 3)] = wr[ii];
            }
        }
        __syncthreads();
    }
}

// ---------------- persistent recurrent kernel ----------------
// R10 structure (h_sm[2], one __syncthreads/step) + R8 primitives at per-warp
// granularity: publish = threadfence(all lanes) + syncwarp + ONE atomicExch
// (warp flag). Consumer: 16 volatile polls + membar.gl.
//
// Safety: pre-MMA barrier at step t joins 8 warps' polls covering all 16x8
// producer warp-flags >= t; a warp-flag = t implies (via that CTA's pre-MMA
// barrier at t-1) its whole CTA finished staging h(t-1) -> overwriting
// g_hbuf[(t+1)&1] (=h(t-1) slot) after our barrier is safe. h_sm[t&1] reuse:
// our staging at t follows barrier(t-1), which every warp reaches only after
// its MMA(t-2) - the last reader of h_sm[t&1].
__global__ __launch_bounds__(256, 1) void rec_kernel() {
    __shared__ __half h_sm[2][16 * 520];

    const int tid = threadIdx.x;
    const int j = blockIdx.x;
    const int bg = j >> 4, cg = j & 15;
    const int w = tid >> 5, lane = tid & 31;
    const int g = lane >> 2, tq = lane & 3;
    const int b = tq >> 1;

    // -------- one-time: B fragments -> registers (128 regs) --------
    unsigned breg[128];
    #pragma unroll
    for (int nt = 0; nt < 2; nt++) {
        const __half* wrow = g_wh + (size_t)(cg * 128 + w * 16 + nt * 8 + g) * DH + 2 * tq;
        #pragma unroll
        for (int kt = 0; kt < 32; kt++) {
            breg[nt * 64 + kt * 2]     = *(const unsigned*)(wrow + kt * 16);
            breg[nt * 64 + kt * 2 + 1] = *(const unsigned*)(wrow + kt * 16 + 8);
        }
    }

    const uint32_t hbase0 = smem_u32(&h_sm[0][0]);
    const int grp = lane >> 3;
    const uint32_t arow = (uint32_t)((((grp & 1) * 8 + (lane & 7)) * 520
                                     + (grp >> 1) * 8) * 2);
    // lanes 0-7 -> producer CTA 2w warps 0-7; lanes 8-15 -> CTA 2w+1
    volatile int* myflag = g_wflags + ((bg * 16 + 2 * w + (lane >> 3)) * 8 + (lane & 7));

    float c0 = 0.f, c1 = 0.f;

    for (int t = 0; t < TT; t++) {
        // xg prefetch (fp16), in flight during the wait
        const __half* xrow0 = g_xg + (size_t)(t * BB + bg * 16 + g) * G4
                              + cg * 128 + w * 16 + 2 * tq;
        const __half* xrow1 = xrow0 + (size_t)8 * G4;
        __half2 x00 = __ldg((const __half2*)xrow0);
        __half2 x01 = __ldg((const __half2*)(xrow0 + 8));
        __half2 x10 = __ldg((const __half2*)xrow1);
        __half2 x11 = __ldg((const __half2*)(xrow1 + 8));

        float acc[2][4];
        acc[0][0] = acc[0][1] = acc[0][2] = acc[0][3] = 0.f;
        acc[1][0] = acc[1][1] = acc[1][2] = acc[1][3] = 0.f;

        if (t > 0) {
            const int s = t & 1;
            // poll 16 producer warp-flags (lanes 0-15)
            if (lane < 16) {
                while (*myflag < t) { }
            }
            __syncwarp();
            asm volatile("membar.gl;" ::: "memory");

            // load producers 2w,2w+1 chunks (2KB) into h_sm[s]
            const uint4* hsrc = (const uint4*)(g_hbuf[s]);
            const int r = lane >> 1, hh = lane & 1;
            #pragma unroll
            for (int ci = 0; ci < 2; ci++) {
                int c = 2 * w + ci;
                #pragma unroll
                for (int jj = 0; jj < 2; jj++) {
                    uint4 v = __ldcg(hsrc + (size_t)(bg * 16 + r) * 64 + c * 4 + hh * 2 + jj);
                    *(uint4*)&h_sm[s][r * 520 + c * 32 + (hh * 2 + jj) * 8] = v;
                }
            }
            __syncthreads();   // all 16 chunks staged (sole per-step barrier)

            // gates += h @ W : 32 kt x 2 HMMA, A via ldmatrix, B in regs
            const uint32_t abase = hbase0 + (uint32_t)s * (16 * 520 * 2) + arow;
            #pragma unroll
            for (int kt = 0; kt < 32; kt++) {
                unsigned a0, a1, a2, a3;
                ldsm_x4(a0, a1, a2, a3, abase + kt * 32);
                mma16816(acc[0][0], acc[0][1], acc[0][2], acc[0][3],
                         a0, a1, a2, a3, breg[kt * 2], breg[kt * 2 + 1]);
                mma16816(acc[1][0], acc[1][1], acc[1][2], acc[1][3],
                         a0, a1, a2, a3, breg[64 + kt * 2], breg[64 + kt * 2 + 1]);
            }
        }

        // add xg
        {
            float2 f;
            f = __half22float2(x00); acc[0][0] += f.x; acc[0][1] += f.y;
            f = __half22float2(x01); acc[1][0] += f.x; acc[1][1] += f.y;
            f = __half22float2(x10); acc[0][2] += f.x; acc[0][3] += f.y;
            f = __half22float2(x11); acc[1][2] += f.x; acc[1][3] += f.y;
        }

        // gate exchange: pair (tq, tq^2); keep e=b slot, send e=1-b slot
        float r00 = __shfl_xor_sync(0xffffffffu, acc[0][1 - b], 2);
        float r01 = __shfl_xor_sync(0xffffffffu, acc[0][3 - b], 2);
        float r10 = __shfl_xor_sync(0xffffffffu, acc[1][1 - b], 2);
        float r11 = __shfl_xor_sync(0xffffffffu, acc[1][3 - b], 2);
        float o00 = acc[0][b],     o01 = acc[0][2 + b];
        float o10 = acc[1][b],     o11 = acc[1][2 + b];

        float zi0 = b ? r00 : o00,  zf0 = b ? o00 : r00;
        float zg0 = b ? r10 : o10,  zo0 = b ? o10 : r10;
        float zi1 = b ? r01 : o01,  zf1 = b ? o01 : r01;
        float zg1 = b ? r11 : o11,  zo1 = b ? o11 : r11;

        float h0 = lstm_cell(zi0, zf0, zg0, zo0, c0);
        float h1 = lstm_cell(zi1, zf1, zg1, zo1, c1);

        const int U = cg * 32 + w * 4 + (((tq & 1) << 1) | b);
        const int row0 = bg * 16 + g, row1 = row0 + 8;

        if (t < TT - 1) {
            __half* hd = g_hbuf[(t + 1) & 1];
            stg_cg_u16(hd + (size_t)row0 * DH + U, __float2half_rn(h0));
            stg_cg_u16(hd + (size_t)row1 * DH + U, __float2half_rn(h1));
            __threadfence();           // each lane orders its own stores
            __syncwarp();
            if (lane == 0) atomicExch(&g_wflags[j * 8 + w], t + 1);
        } else {
            g_hlast[(size_t)row0 * DH + U] = h0;
            g_hlast[(size_t)row1 * DH + U] = h1;
        }
    }
}

// ---------------- final FC ----------------
__global__ void fc_kernel(const float* __restrict__ w_fc, const float* __restrict__ b_fc,
                          float* __restrict__ out) {
    __shared__ float hs[DH];
    int bb = blockIdx.x, o = threadIdx.x;
    for (int i = o; i < DH; i += 256) hs[i] = g_hlast[bb * DH + i];
    __syncthreads();
    float acc = b_fc[o];
    #pragma unroll 8
    for (int k = 0; k < DH; k++) acc = fmaf(hs[k], w_fc[(size_t)k * DOUT + o], acc);
    out[bb * DOUT + o] = acc;
}

// ---------------- launch ----------------
extern "C" void kernel_launch(void* const* d_in, const int* in_sizes, int n_in,
                              void* d_out, int out_size) {
    (void)in_sizes; (void)n_in; (void)out_size;
    const float* x     = (const float*)d_in[0];
    const float* w_x2h = (const float*)d_in[1];
    const float* b_x2h = (const float*)d_in[2];
    const float* w_h2h = (const float*)d_in[3];
    const float* b_h2h = (const float*)d_in[4];
    const float* w_fc  = (const float*)d_in[5];
    const float* b_fc  = (const float*)d_in[6];
    float* out = (float*)d_out;

    cudaFuncSetAttribute(gemm1_kernel, cudaFuncAttributeMaxDynamicSharedMemorySize, G1_SMEM);

    prep_w_kernel<<<4096, 256>>>(w_x2h, b_x2h, w_h2h, b_h2h);
    gemm1_kernel<<<512, 256, G1_SMEM>>>(x);
    rec_kernel<<<RCTA, 256>>>();
    fc_kernel<<<BB, 256>>>(w_fc, b_fc, out);
}

// round 14
// speedup vs baseline: 1.2672x; 1.0064x over previous
#include <cuda_runtime.h>
#include <cuda_fp16.h>
#include <cstdint>

// Problem dims
#define BB    128
#define TT    512
#define DIN   256
#define DH    512
#define G4    2048        // 4*DH
#define DOUT  256
#define RCTA  128         // 8 batch groups x 16 col groups

// ---------------- static device scratch ----------------
__device__ __half g_wx [(size_t)G4 * DIN];            // w_x2h permuted, [p][k] (1MB, L2)
__device__ __half g_wh [(size_t)G4 * DH];             // w_h2h permuted, [p][k]
__device__ float  g_gbias[G4];                        // permuted biases
__device__ __half g_xg [(size_t)BB * TT * G4];        // xg fp16, [m][p]
__device__ __half g_hbuf[2][BB * DH];                 // double-buffered h (fp16, L2)
__device__ float  g_hlast[BB * DH];                   // final h fp32
__device__ int    g_flags[RCTA];                      // per-CTA publish flags

// permuted gate column: p = cg*128 + w*16 + q*4 + u
//   cg = p>>7, w = (p>>4)&7 (warp), q = (p>>2)&3 (gate), u = p&3 (unit)
// original col = q*512 + (hidden unit = cg*32 + w*4 + u)
__device__ __forceinline__ int gate_col(int p) {
    return ((p >> 2) & 3) * DH + (p >> 7) * 32 + (((p >> 4) & 7) << 2) + (p & 3);
}

__device__ __forceinline__ void mma16816(float& d0, float& d1, float& d2, float& d3,
                                         unsigned a0, unsigned a1, unsigned a2, unsigned a3,
                                         unsigned b0, unsigned b1) {
    asm volatile(
        "mma.sync.aligned.m16n8k16.row.col.f32.f16.f16.f32 "
        "{%0,%1,%2,%3}, {%4,%5,%6,%7}, {%8,%9}, {%0,%1,%2,%3};"
        : "+f"(d0), "+f"(d1), "+f"(d2), "+f"(d3)
        : "r"(a0), "r"(a1), "r"(a2), "r"(a3), "r"(b0), "r"(b1));
}

__device__ __forceinline__ void ldsm_x4(unsigned& a0, unsigned& a1, unsigned& a2, unsigned& a3,
                                        uint32_t addr) {
    asm volatile("ldmatrix.sync.aligned.m8n8.x4.shared.b16 {%0,%1,%2,%3}, [%4];"
                 : "=r"(a0), "=r"(a1), "=r"(a2), "=r"(a3) : "r"(addr));
}

__device__ __forceinline__ uint32_t smem_u32(const void* p) {
    uint32_t a;
    asm("{ .reg .u64 t; cvta.to.shared.u64 t, %1; cvt.u32.u64 %0, t; }" : "=r"(a) : "l"(p));
    return a;
}

__device__ __forceinline__ void stg_cg_u16(__half* p, __half v) {
    unsigned short s = __half_as_ushort(v);
    asm volatile("st.global.cg.u16 [%0], %1;" :: "l"(p), "h"(s) : "memory");
}

__device__ __forceinline__ float sigm(float x) { return 1.0f / (1.0f + __expf(-x)); }
__device__ __forceinline__ float tanh_a(float x) {
    x = fminf(fmaxf(x, -15.f), 15.f);
    float e = __expf(2.f * x);
    return (e - 1.f) / (e + 1.f);
}
__device__ __forceinline__ float lstm_cell(float zi, float zf, float zg, float zo, float& c) {
    float i = sigm(zi), f = sigm(zf), gg = tanh_a(zg), o = sigm(zo);
    c = fmaf(c, f, i * gg);
    return o * tanh_a(c);
}

// ---------------- prep: weights/biases/flags ----------------
__global__ void prep_w_kernel(const float* __restrict__ w_x2h, const float* __restrict__ b_x2h,
                              const float* __restrict__ w_h2h, const float* __restrict__ b_h2h) {
    int idx = blockIdx.x * 256 + threadIdx.x;   // 1,048,576 = 2048*512
    {
        int p = idx >> 9, k = idx & 511;
        g_wh[idx] = __float2half_rn(w_h2h[(size_t)k * G4 + gate_col(p)]);
    }
    if (idx < G4 * DIN) {
        int p = idx >> 8, k = idx & 255;
        g_wx[idx] = __float2half_rn(w_x2h[(size_t)k * G4 + gate_col(p)]);
    }
    if (idx < G4) {
        int gc = gate_col(idx);
        g_gbias[idx] = b_x2h[gc] + b_h2h[gc];
    }
    if (idx < RCTA) g_flags[idx] = 0;
}

// ---------------- GEMM1 v2 (proven R11): one block per m-tile, fused x convert ----------------
// grid 512 (t), block 256. x tile resident in smem; loop 32 n-slabs of 64 cols
// with register-prefetch double-buffered w_sm (g_wx is 1MB -> L2-resident).
#define G1_SMEM ((128 * 264 + 2 * 64 * 264) * 2)
__global__ __launch_bounds__(256, 1) void gemm1_kernel(const float* __restrict__ x) {
    extern __shared__ __half sm[];
    __half* x_sm = sm;                       // 128 x 264 (K=256 + pad)
    __half* w_sm = sm + 128 * 264;           // 2 x (64 x 264)
    const int tid = threadIdx.x;
    const int t = blockIdx.x;
    const int m0 = t * 128;

    // fused load+convert: row b <- x[b][t][:]  (fp32, contiguous 256)
    #pragma unroll 8
    for (int ii = 0; ii < 32; ii++) {
        int i = tid + ii * 256;              // 8192 float4 total
        int r = i >> 6, f4 = i & 63;
        float4 v = *(const float4*)(x + ((size_t)r * TT + t) * DIN + f4 * 4);
        __half2 h0 = __floats2half2_rn(v.x, v.y);
        __half2 h1 = __floats2half2_rn(v.z, v.w);
        *(__half2*)&x_sm[r * 264 + f4 * 4]     = h0;
        *(__half2*)&x_sm[r * 264 + f4 * 4 + 2] = h1;
    }

    const int w = tid >> 5, lane = tid & 31, g = lane >> 2, q = lane & 3;
    const int r0 = 16 * w + g;
    const int grp = lane >> 3;
    const uint32_t xbase = smem_u32(x_sm);
    const uint32_t abase = xbase + (uint32_t)(((16 * w + (grp & 1) * 8 + (lane & 7)) * 264
                                               + (grp >> 1) * 8) * 2);

    // preload w tile 0 into regs
    uint4 wr[8];
    const uint4* ws = (const uint4*)g_wx;
    #pragma unroll
    for (int ii = 0; ii < 8; ii++) {
        int i = tid + ii * 256;
        wr[ii] = ws[i];                      // tile 0: rows 0..63
    }
    {
        #pragma unroll
        for (int ii = 0; ii < 8; ii++) {
            int i = tid + ii * 256;
            *(uint4*)&w_sm[(i >> 5) * 264 + ((i & 31) << 3)] = wr[ii];
        }
    }
    __syncthreads();

    for (int nt64 = 0; nt64 < 32; nt64++) {
        const int cur = nt64 & 1;
        const __half* wc = w_sm + cur * (64 * 264);
        const int n0 = nt64 * 64;

        if (nt64 < 31) {                     // prefetch next tile into regs
            const uint4* wsn = ws + (size_t)(n0 + 64) * 32;
            #pragma unroll
            for (int ii = 0; ii < 8; ii++) {
                int i = tid + ii * 256;
                wr[ii] = wsn[i];
            }
        }

        float acc[8][4];
        #pragma unroll
        for (int nt = 0; nt < 8; nt++) { acc[nt][0] = acc[nt][1] = acc[nt][2] = acc[nt][3] = 0.f; }

        #pragma unroll 4
        for (int kt = 0; kt < 16; kt++) {
            int k0 = kt * 16 + 2 * q;
            unsigned a0, a1, a2, a3;
            ldsm_x4(a0, a1, a2, a3, abase + kt * 32);
            #pragma unroll
            for (int nt = 0; nt < 8; nt++) {
                unsigned b0 = *(const unsigned*)&wc[(8 * nt + g) * 264 + k0];
                unsigned b1 = *(const unsigned*)&wc[(8 * nt + g) * 264 + k0 + 8];
                mma16816(acc[nt][0], acc[nt][1], acc[nt][2], acc[nt][3], a0, a1, a2, a3, b0, b1);
            }
        }

        #pragma unroll
        for (int nt = 0; nt < 8; nt++) {
            int p = n0 + 8 * nt + 2 * q;
            float2 gb = *(const float2*)&g_gbias[p];
            *(__half2*)&g_xg[(size_t)(m0 + r0) * G4 + p] =
                __floats2half2_rn(acc[nt][0] + gb.x, acc[nt][1] + gb.y);
            *(__half2*)&g_xg[(size_t)(m0 + r0 + 8) * G4 + p] =
                __floats2half2_rn(acc[nt][2] + gb.x, acc[nt][3] + gb.y);
        }

        if (nt64 < 31) {                     // stage next tile (other buffer)
            __half* wn = w_sm + (cur ^ 1) * (64 * 264);
            #pragma unroll
            for (int ii = 0; ii < 8; ii++) {
                int i = tid + ii * 256;
                *(uint4*)&wn[(i >> 5) * 264 + ((i & 31) << 3)] = wr[ii];
            }
        }
        __syncthreads();
    }
}

// ---------------- persistent recurrent kernel (R8 verbatim — proven 2176us) ----------------
__global__ __launch_bounds__(256, 1) void rec_kernel() {
    __shared__ __half h_sm[16 * 520];      // A tile: 16 rows x 512 (+8 pad)

    const int tid = threadIdx.x;
    const int j = blockIdx.x;
    const int bg = j >> 4, cg = j & 15;
    const int w = tid >> 5, lane = tid & 31;
    const int g = lane >> 2, tq = lane & 3;
    const int b = tq >> 1;

    // -------- one-time: B fragments -> registers (128 regs) --------
    unsigned breg[128];
    #pragma unroll
    for (int nt = 0; nt < 2; nt++) {
        const __half* wrow = g_wh + (size_t)(cg * 128 + w * 16 + nt * 8 + g) * DH + 2 * tq;
        #pragma unroll
        for (int kt = 0; kt < 32; kt++) {
            breg[nt * 64 + kt * 2]     = *(const unsigned*)(wrow + kt * 16);
            breg[nt * 64 + kt * 2 + 1] = *(const unsigned*)(wrow + kt * 16 + 8);
        }
    }

    // ldmatrix per-lane base
    const uint32_t hbase = smem_u32(h_sm);
    const int grp = lane >> 3;
    const uint32_t abase = hbase + (uint32_t)((((grp & 1) * 8 + (lane & 7)) * 520
                                               + (grp >> 1) * 8) * 2);

    float c0 = 0.f, c1 = 0.f;      // cell state: 2 rows x 1 unit per thread

    for (int t = 0; t < TT; t++) {
        // xg prefetch (fp16), in flight during the wait
        const __half* xrow0 = g_xg + (size_t)(t * BB + bg * 16 + g) * G4
                              + cg * 128 + w * 16 + 2 * tq;
        const __half* xrow1 = xrow0 + (size_t)8 * G4;
        __half2 x00 = __ldg((const __half2*)xrow0);
        __half2 x01 = __ldg((const __half2*)(xrow0 + 8));
        __half2 x10 = __ldg((const __half2*)xrow1);
        __half2 x11 = __ldg((const __half2*)(xrow1 + 8));

        float acc[2][4];
        acc[0][0] = acc[0][1] = acc[0][2] = acc[0][3] = 0.f;
        acc[1][0] = acc[1][1] = acc[1][2] = acc[1][3] = 0.f;

        if (t > 0) {
            // per-warp: wait for producers 2w, 2w+1; load their chunks (2KB)
            if (lane < 2) {
                volatile int* fl = g_flags + bg * 16 + 2 * w + lane;
                while (*fl < t) { }
            }
            __syncwarp();
            asm volatile("membar.gl;" ::: "memory");

            const uint4* hsrc = (const uint4*)(g_hbuf[t & 1]);
            const int r = lane >> 1, hh = lane & 1;
            #pragma unroll
            for (int ci = 0; ci < 2; ci++) {
                int c = 2 * w + ci;
                #pragma unroll
                for (int jj = 0; jj < 2; jj++) {
                    uint4 v = __ldcg(hsrc + (size_t)(bg * 16 + r) * 64 + c * 4 + hh * 2 + jj);
                    *(uint4*)&h_sm[r * 520 + c * 32 + (hh * 2 + jj) * 8] = v;
                }
            }
            __syncthreads();

            // gates += h @ W : 32 kt x 2 HMMA, A via ldmatrix, B in regs
            #pragma unroll
            for (int kt = 0; kt < 32; kt++) {
                unsigned a0, a1, a2, a3;
                ldsm_x4(a0, a1, a2, a3, abase + kt * 32);
                mma16816(acc[0][0], acc[0][1], acc[0][2], acc[0][3],
                         a0, a1, a2, a3, breg[kt * 2], breg[kt * 2 + 1]);
                mma16816(acc[1][0], acc[1][1], acc[1][2], acc[1][3],
                         a0, a1, a2, a3, breg[64 + kt * 2], breg[64 + kt * 2 + 1]);
            }
        }

        // add xg
        {
            float2 f;
            f = __half22float2(x00); acc[0][0] += f.x; acc[0][1] += f.y;
            f = __half22float2(x01); acc[1][0] += f.x; acc[1][1] += f.y;
            f = __half22float2(x10); acc[0][2] += f.x; acc[0][3] += f.y;
            f = __half22float2(x11); acc[1][2] += f.x; acc[1][3] += f.y;
        }

        // gate exchange: pair (tq, tq^2); keep e=b slot, send e=1-b slot
        float r00 = __shfl_xor_sync(0xffffffffu, acc[0][1 - b], 2);
        float r01 = __shfl_xor_sync(0xffffffffu, acc[0][3 - b], 2);
        float r10 = __shfl_xor_sync(0xffffffffu, acc[1][1 - b], 2);
        float r11 = __shfl_xor_sync(0xffffffffu, acc[1][3 - b], 2);
        float o00 = acc[0][b],     o01 = acc[0][2 + b];
        float o10 = acc[1][b],     o11 = acc[1][2 + b];

        float zi0 = b ? r00 : o00,  zf0 = b ? o00 : r00;
        float zg0 = b ? r10 : o10,  zo0 = b ? o10 : r10;
        float zi1 = b ? r01 : o01,  zf1 = b ? o01 : r01;
        float zg1 = b ? r11 : o11,  zo1 = b ? o11 : r11;

        float h0 = lstm_cell(zi0, zf0, zg0, zo0, c0);
        float h1 = lstm_cell(zi1, zf1, zg1, zo1, c1);

        const int U = cg * 32 + w * 4 + (((tq & 1) << 1) | b);
        const int row0 = bg * 16 + g, row1 = row0 + 8;

        if (t < TT - 1) {
            __half* hd = g_hbuf[(t + 1) & 1];
            stg_cg_u16(hd + (size_t)row0 * DH + U, __float2half_rn(h0));
            stg_cg_u16(hd + (size_t)row1 * DH + U, __float2half_rn(h1));
            __threadfence();
            __syncthreads();
            if (tid == 0) atomicExch(&g_flags[j], t + 1);
        } else {
            g_hlast[(size_t)row0 * DH + U] = h0;
            g_hlast[(size_t)row1 * DH + U] = h1;
        }
    }
}

// ---------------- final FC (v1, proven): out = hlast @ w_fc + b_fc ----------------
__global__ void fc_kernel(const float* __restrict__ w_fc, const float* __restrict__ b_fc,
                          float* __restrict__ out) {
    __shared__ float hs[DH];
    int bb = blockIdx.x, o = threadIdx.x;
    for (int i = o; i < DH; i += 256) hs[i] = g_hlast[bb * DH + i];
    __syncthreads();
    float acc = b_fc[o];
    #pragma unroll 8
    for (int k = 0; k < DH; k++) acc = fmaf(hs[k], w_fc[(size_t)k * DOUT + o], acc);
    out[bb * DOUT + o] = acc;
}

// ---------------- launch ----------------
extern "C" void kernel_launch(void* const* d_in, const int* in_sizes, int n_in,
                              void* d_out, int out_size) {
    (void)in_sizes; (void)n_in; (void)out_size;
    const float* x     = (const float*)d_in[0];
    const float* w_x2h = (const float*)d_in[1];
    const float* b_x2h = (const float*)d_in[2];
    const float* w_h2h = (const float*)d_in[3];
    const float* b_h2h = (const float*)d_in[4];
    const float* w_fc  = (const float*)d_in[5];
    const float* b_fc  = (const float*)d_in[6];
    float* out = (float*)d_out;

    cudaFuncSetAttribute(gemm1_kernel, cudaFuncAttributeMaxDynamicSharedMemorySize, G1_SMEM);

    prep_w_kernel<<<4096, 256>>>(w_x2h, b_x2h, w_h2h, b_h2h);
    gemm1_kernel<<<512, 256, G1_SMEM>>>(x);
    rec_kernel<<<RCTA, 256>>>();
    fc_kernel<<<BB, 256>>>(w_fc, b_fc, out);
}

// round 15
// speedup vs baseline: 1.4360x; 1.1332x over previous
#include <cuda_runtime.h>
#include <cuda_fp16.h>
#include <cstdint>

// Problem dims
#define BB    128
#define TT    512
#define DIN   256
#define DH    512
#define G4    2048        // 4*DH
#define DOUT  256
#define RCTA  128         // 8 batch groups x 16 col groups

// ---------------- static device scratch ----------------
__device__ __half g_x_h[(size_t)BB * TT * DIN];       // x fp16, [m=t*128+b][k]
__device__ __half g_wx [(size_t)G4 * DIN];            // w_x2h permuted, [p][k]
__device__ __half g_wh [(size_t)G4 * DH];             // w_h2h permuted, [p][k]
__device__ float  g_gbias[G4];                        // permuted biases
__device__ __half g_xg [(size_t)BB * TT * G4];        // xg fp16, [m][p]
// h double buffer, CHUNK-MAJOR: [buf][bg][cg][16 rows][32 units]
__device__ __half g_hbuf[2][BB * DH];
__device__ float  g_hlast[BB * DH];                   // final h fp32
__device__ int    g_flags[RCTA];                      // per-CTA publish flags

// permuted gate column: p = cg*128 + w*16 + q*4 + u
//   cg = p>>7, w = (p>>4)&7 (warp), q = (p>>2)&3 (gate), u = p&3 (unit)
// original col = q*512 + (hidden unit = cg*32 + w*4 + u)
__device__ __forceinline__ int gate_col(int p) {
    return ((p >> 2) & 3) * DH + (p >> 7) * 32 + (((p >> 4) & 7) << 2) + (p & 3);
}

__device__ __forceinline__ void mma16816(float& d0, float& d1, float& d2, float& d3,
                                         unsigned a0, unsigned a1, unsigned a2, unsigned a3,
                                         unsigned b0, unsigned b1) {
    asm volatile(
        "mma.sync.aligned.m16n8k16.row.col.f32.f16.f16.f32 "
        "{%0,%1,%2,%3}, {%4,%5,%6,%7}, {%8,%9}, {%0,%1,%2,%3};"
        : "+f"(d0), "+f"(d1), "+f"(d2), "+f"(d3)
        : "r"(a0), "r"(a1), "r"(a2), "r"(a3), "r"(b0), "r"(b1));
}

__device__ __forceinline__ void ldsm_x4(unsigned& a0, unsigned& a1, unsigned& a2, unsigned& a3,
                                        uint32_t addr) {
    asm volatile("ldmatrix.sync.aligned.m8n8.x4.shared.b16 {%0,%1,%2,%3}, [%4];"
                 : "=r"(a0), "=r"(a1), "=r"(a2), "=r"(a3) : "r"(addr));
}

__device__ __forceinline__ uint32_t smem_u32(const void* p) {
    uint32_t a;
    asm("{ .reg .u64 t; cvta.to.shared.u64 t, %1; cvt.u32.u64 %0, t; }" : "=r"(a) : "l"(p));
    return a;
}

__device__ __forceinline__ void stg_cg_u16(__half* p, __half v) {
    unsigned short s = __half_as_ushort(v);
    asm volatile("st.global.cg.u16 [%0], %1;" :: "l"(p), "h"(s) : "memory");
}

__device__ __forceinline__ float sigm(float x) { return 1.0f / (1.0f + __expf(-x)); }
__device__ __forceinline__ float tanh_a(float x) {
    x = fminf(fmaxf(x, -15.f), 15.f);
    float e = __expf(2.f * x);
    return (e - 1.f) / (e + 1.f);
}
__device__ __forceinline__ float lstm_cell(float zi, float zf, float zg, float zo, float& c) {
    float i = sigm(zi), f = sigm(zf), gg = tanh_a(zg), o = sigm(zo);
    c = fmaf(c, f, i * gg);
    return o * tanh_a(c);
}

// ---------------- prep kernels (R8 verbatim) ----------------
__global__ void prep_x_kernel(const float* __restrict__ x) {
    size_t idx = (size_t)blockIdx.x * 256 + threadIdx.x;
    int k = idx & 255;
    int m = (int)(idx >> 8);
    int t = m >> 7, b = m & 127;
    g_x_h[idx] = __float2half_rn(x[((size_t)b * TT + t) * DIN + k]);
}

__global__ void prep_w_kernel(const float* __restrict__ w_x2h, const float* __restrict__ b_x2h,
                              const float* __restrict__ w_h2h, const float* __restrict__ b_h2h) {
    int idx = blockIdx.x * 256 + threadIdx.x;   // 1,048,576 = 2048*512
    {
        int p = idx >> 9, k = idx & 511;
        g_wh[idx] = __float2half_rn(w_h2h[(size_t)k * G4 + gate_col(p)]);
    }
    if (idx < G4 * DIN) {
        int p = idx >> 8, k = idx & 255;
        g_wx[idx] = __float2half_rn(w_x2h[(size_t)k * G4 + gate_col(p)]);
    }
    if (idx < G4) {
        int gc = gate_col(idx);
        g_gbias[idx] = b_x2h[gc] + b_h2h[gc];
    }
    if (idx < RCTA) g_flags[idx] = 0;
}

// ---------------- GEMM1 v1 (R8 verbatim): xg = x @ wx + bias (fp16 out) ----------------
#define G1_SMEM ((128 * 264 + 64 * 264) * 2)
__global__ __launch_bounds__(256, 1) void gemm1_kernel() {
    extern __shared__ __half sm[];
    __half* x_sm = sm;                 // 128 x 264
    __half* w_sm = sm + 128 * 264;     // 64  x 264
    const int tid = threadIdx.x;
    const int m0 = blockIdx.y * 128, n0 = blockIdx.x * 64;

    const uint4* xs = (const uint4*)g_x_h;
    #pragma unroll 4
    for (int i = tid; i < 4096; i += 256) {
        int r = i >> 5, k8 = (i & 31) << 3;
        *(uint4*)&x_sm[r * 264 + k8] = xs[(size_t)(m0 + r) * 32 + (i & 31)];
    }
    const uint4* ws = (const uint4*)g_wx;
    #pragma unroll 4
    for (int i = tid; i < 2048; i += 256) {
        int c = i >> 5, k8 = (i & 31) << 3;
        *(uint4*)&w_sm[c * 264 + k8] = ws[(size_t)(n0 + c) * 32 + (i & 31)];
    }
    __syncthreads();

    const int w = tid >> 5, lane = tid & 31, g = lane >> 2, q = lane & 3;
    const int r0 = 16 * w + g;
    float acc[8][4];
    #pragma unroll
    for (int nt = 0; nt < 8; nt++) { acc[nt][0] = acc[nt][1] = acc[nt][2] = acc[nt][3] = 0.f; }

    #pragma unroll 4
    for (int kt = 0; kt < 16; kt++) {
        int k0 = kt * 16 + 2 * q;
        unsigned a0 = *(const unsigned*)&x_sm[r0 * 264 + k0];
        unsigned a1 = *(const unsigned*)&x_sm[(r0 + 8) * 264 + k0];
        unsigned a2 = *(const unsigned*)&x_sm[r0 * 264 + k0 + 8];
        unsigned a3 = *(const unsigned*)&x_sm[(r0 + 8) * 264 + k0 + 8];
        #pragma unroll
        for (int nt = 0; nt < 8; nt++) {
            unsigned b0 = *(const unsigned*)&w_sm[(8 * nt + g) * 264 + k0];
            unsigned b1 = *(const unsigned*)&w_sm[(8 * nt + g) * 264 + k0 + 8];
            mma16816(acc[nt][0], acc[nt][1], acc[nt][2], acc[nt][3], a0, a1, a2, a3, b0, b1);
        }
    }
    #pragma unroll
    for (int nt = 0; nt < 8; nt++) {
        int p = n0 + 8 * nt + 2 * q;
        float2 gb = *(const float2*)&g_gbias[p];
        *(__half2*)&g_xg[(size_t)(m0 + r0) * G4 + p] =
            __floats2half2_rn(acc[nt][0] + gb.x, acc[nt][1] + gb.y);
        *(__half2*)&g_xg[(size_t)(m0 + r0 + 8) * G4 + p] =
            __floats2half2_rn(acc[nt][2] + gb.x, acc[nt][3] + gb.y);
    }
}

// ---------------- persistent recurrent kernel ----------------
// R8 protocol verbatim (poll lane<2, membar.gl, pre-MMA sync, threadfence +
// publish sync + 1 atomicExch). New: chunk-major g_hbuf (coalesced 2KB/warp
// loads), padded chunked h_sm (stride 40 halves, conflict-free ldmatrix),
// 4 accumulator chains (kt parity).
#define CH_STRIDE 40                       // halves per row in smem chunk
#define CH_SZ     (16 * CH_STRIDE)         // 640 halves per chunk
__global__ __launch_bounds__(256, 1) void rec_kernel() {
    __shared__ __half h_sm[16 * CH_SZ];    // 16 chunks x 16 rows x 40 halves (20KB)

    const int tid = threadIdx.x;
    const int j = blockIdx.x;
    const int bg = j >> 4, cg = j & 15;
    const int w = tid >> 5, lane = tid & 31;
    const int g = lane >> 2, tq = lane & 3;
    const int b = tq >> 1;

    // -------- one-time: B fragments -> registers (128 regs) --------
    unsigned breg[128];
    #pragma unroll
    for (int nt = 0; nt < 2; nt++) {
        const __half* wrow = g_wh + (size_t)(cg * 128 + w * 16 + nt * 8 + g) * DH + 2 * tq;
        #pragma unroll
        for (int kt = 0; kt < 32; kt++) {
            breg[nt * 64 + kt * 2]     = *(const unsigned*)(wrow + kt * 16);
            breg[nt * 64 + kt * 2 + 1] = *(const unsigned*)(wrow + kt * 16 + 8);
        }
    }

    // ldmatrix per-lane offset inside a chunk (halves):
    // grp&1 -> row half (0/8), grp>>1 -> k half (+8)
    const uint32_t hbase = smem_u32(h_sm);
    const int grp = lane >> 3;
    const uint32_t laneoff = (uint32_t)(((grp & 1) * 8 + (lane & 7)) * CH_STRIDE
                                        + (grp >> 1) * 8);

    float c0 = 0.f, c1 = 0.f;      // cell state: 2 rows x 1 unit per thread

    for (int t = 0; t < TT; t++) {
        // xg prefetch (fp16), in flight during the wait
        const __half* xrow0 = g_xg + (size_t)(t * BB + bg * 16 + g) * G4
                              + cg * 128 + w * 16 + 2 * tq;
        const __half* xrow1 = xrow0 + (size_t)8 * G4;
        __half2 x00 = __ldg((const __half2*)xrow0);
        __half2 x01 = __ldg((const __half2*)(xrow0 + 8));
        __half2 x10 = __ldg((const __half2*)xrow1);
        __half2 x11 = __ldg((const __half2*)(xrow1 + 8));

        float accA[2][4], accB[2][4];
        #pragma unroll
        for (int nt = 0; nt < 2; nt++)
            #pragma unroll
            for (int e = 0; e < 4; e++) { accA[nt][e] = 0.f; accB[nt][e] = 0.f; }

        if (t > 0) {
            // per-warp: wait for producers 2w, 2w+1 (R8 protocol)
            if (lane < 2) {
                volatile int* fl = g_flags + bg * 16 + 2 * w + lane;
                while (*fl < t) { }
            }
            __syncwarp();
            asm volatile("membar.gl;" ::: "memory");

            // coalesced: chunks 2w,2w+1 are 1KB contiguous each in gmem
            const uint4* hsrc = (const uint4*)(g_hbuf[t & 1]);
            #pragma unroll
            for (int ci = 0; ci < 2; ci++) {
                const int c = 2 * w + ci;
                const uint4* cb = hsrc + (size_t)(bg * 16 + c) * 64;
                #pragma unroll
                for (int jj = 0; jj < 2; jj++) {
                    int n = lane + jj * 32;                 // 0..63
                    uint4 v = __ldcg(cb + n);
                    *(uint4*)&h_sm[c * CH_SZ + (n >> 2) * CH_STRIDE + (n & 3) * 8] = v;
                }
            }
            __syncthreads();

            // gates += h @ W : 32 kt, A via conflict-free ldmatrix, B in regs,
            // 4 accumulator chains (kt parity)
            #pragma unroll
            for (int kt = 0; kt < 32; kt++) {
                const uint32_t a_addr = hbase
                    + (uint32_t)(((kt >> 1) * CH_SZ + (kt & 1) * 16) * 2) + laneoff * 2;
                unsigned a0, a1, a2, a3;
                ldsm_x4(a0, a1, a2, a3, a_addr);
                if (kt & 1) {
                    mma16816(accB[0][0], accB[0][1], accB[0][2], accB[0][3],
                             a0, a1, a2, a3, breg[kt * 2], breg[kt * 2 + 1]);
                    mma16816(accB[1][0], accB[1][1], accB[1][2], accB[1][3],
                             a0, a1, a2, a3, breg[64 + kt * 2], breg[64 + kt * 2 + 1]);
                } else {
                    mma16816(accA[0][0], accA[0][1], accA[0][2], accA[0][3],
                             a0, a1, a2, a3, breg[kt * 2], breg[kt * 2 + 1]);
                    mma16816(accA[1][0], accA[1][1], accA[1][2], accA[1][3],
                             a0, a1, a2, a3, breg[64 + kt * 2], breg[64 + kt * 2 + 1]);
                }
            }
        }

        // combine chains + add xg
        float acc[2][4];
        #pragma unroll
        for (int nt = 0; nt < 2; nt++)
            #pragma unroll
            for (int e = 0; e < 4; e++) acc[nt][e] = accA[nt][e] + accB[nt][e];
        {
            float2 f;
            f = __half22float2(x00); acc[0][0] += f.x; acc[0][1] += f.y;
            f = __half22float2(x01); acc[1][0] += f.x; acc[1][1] += f.y;
            f = __half22float2(x10); acc[0][2] += f.x; acc[0][3] += f.y;
            f = __half22float2(x11); acc[1][2] += f.x; acc[1][3] += f.y;
        }

        // gate exchange: pair (tq, tq^2); keep e=b slot, send e=1-b slot
        float r00 = __shfl_xor_sync(0xffffffffu, acc[0][1 - b], 2);
        float r01 = __shfl_xor_sync(0xffffffffu, acc[0][3 - b], 2);
        float r10 = __shfl_xor_sync(0xffffffffu, acc[1][1 - b], 2);
        float r11 = __shfl_xor_sync(0xffffffffu, acc[1][3 - b], 2);
        float o00 = acc[0][b],     o01 = acc[0][2 + b];
        float o10 = acc[1][b],     o11 = acc[1][2 + b];

        float zi0 = b ? r00 : o00,  zf0 = b ? o00 : r00;
        float zg0 = b ? r10 : o10,  zo0 = b ? o10 : r10;
        float zi1 = b ? r01 : o01,  zf1 = b ? o01 : r01;
        float zg1 = b ? r11 : o11,  zo1 = b ? o11 : r11;

        float h0 = lstm_cell(zi0, zf0, zg0, zo0, c0);
        float h1 = lstm_cell(zi1, zf1, zg1, zo1, c1);

        const int ul = w * 4 + (((tq & 1) << 1) | b);   // unit within chunk

        if (t < TT - 1) {
            // chunk-major store: g_hbuf[buf][(bg*16+cg)*16 + row][32 units]
            __half* hd = g_hbuf[(t + 1) & 1] + ((size_t)(bg * 16 + cg) * 16) * 32;
            stg_cg_u16(hd + g * 32 + ul,       __float2half_rn(h0));
            stg_cg_u16(hd + (g + 8) * 32 + ul, __float2half_rn(h1));
            __threadfence();
            __syncthreads();
            if (tid == 0) atomicExch(&g_flags[j], t + 1);
        } else {
            const int U = cg * 32 + ul;
            const int row0 = bg * 16 + g, row1 = row0 + 8;
            g_hlast[(size_t)row0 * DH + U] = h0;
            g_hlast[(size_t)row1 * DH + U] = h1;
        }
    }
}

// ---------------- final FC: 4 independent accumulator chains ----------------
__global__ void fc_kernel(const float* __restrict__ w_fc, const float* __restrict__ b_fc,
                          float* __restrict__ out) {
    __shared__ float hs[DH];
    int bb = blockIdx.x, o = threadIdx.x;
    for (int i = o; i < DH; i += 256) hs[i] = g_hlast[bb * DH + i];
    __syncthreads();
    float a0 = 0.f, a1 = 0.f, a2 = 0.f, a3 = 0.f;
    #pragma unroll 8
    for (int k = 0; k < DH; k += 4) {
        a0 = fmaf(hs[k],     w_fc[(size_t)k * DOUT + o],       a0);
        a1 = fmaf(hs[k + 1], w_fc[(size_t)(k + 1) * DOUT + o], a1);
        a2 = fmaf(hs[k + 2], w_fc[(size_t)(k + 2) * DOUT + o], a2);
        a3 = fmaf(hs[k + 3], w_fc[(size_t)(k + 3) * DOUT + o], a3);
    }
    out[bb * DOUT + o] = (a0 + a1) + (a2 + a3) + b_fc[o];
}

// ---------------- launch ----------------
extern "C" void kernel_launch(void* const* d_in, const int* in_sizes, int n_in,
                              void* d_out, int out_size) {
    (void)in_sizes; (void)n_in; (void)out_size;
    const float* x     = (const float*)d_in[0];
    const float* w_x2h = (const float*)d_in[1];
    const float* b_x2h = (const float*)d_in[2];
    const float* w_h2h = (const float*)d_in[3];
    const float* b_h2h = (const float*)d_in[4];
    const float* w_fc  = (const float*)d_in[5];
    const float* b_fc  = (const float*)d_in[6];
    float* out = (float*)d_out;

    cudaFuncSetAttribute(gemm1_kernel, cudaFuncAttributeMaxDynamicSharedMemorySize, G1_SMEM);

    prep_x_kernel<<<65536, 256>>>(x);
    prep_w_kernel<<<4096, 256>>>(w_x2h, b_x2h, w_h2h, b_h2h);
    gemm1_kernel<<<dim3(32, 512), 256, G1_SMEM>>>();
    rec_kernel<<<RCTA, 256>>>();
    fc_kernel<<<BB, 256>>>(w_fc, b_fc, out);
}

// round 16
// speedup vs baseline: 1.7116x; 1.1919x over previous
#include <cuda_runtime.h>
#include <cuda_fp16.h>
#include <cstdint>

// Problem dims
#define BB    128
#define TT    512
#define DIN   256
#define DH    512
#define G4    2048        // 4*DH
#define DOUT  256
#define RCTA  128         // 8 batch groups x 16 col groups

// ---------------- static device scratch ----------------
__device__ __half g_x_h[(size_t)BB * TT * DIN];       // x fp16, [m=t*128+b][k]
__device__ __half g_wx [(size_t)G4 * DIN];            // w_x2h permuted, [p][k]
__device__ __half g_wh [(size_t)G4 * DH];             // w_h2h permuted, [p][k]
__device__ float  g_gbias[G4];                        // permuted biases
// h double buffer, CHUNK-MAJOR: [buf][bg][cg][16 rows][32 units]
__device__ __half g_hbuf[2][BB * DH];
__device__ float  g_hlast[BB * DH];                   // final h fp32
__device__ int    g_flags[RCTA];                      // per-CTA publish flags

// permuted gate column: p = cg*128 + w*16 + q*4 + u
__device__ __forceinline__ int gate_col(int p) {
    return ((p >> 2) & 3) * DH + (p >> 7) * 32 + (((p >> 4) & 7) << 2) + (p & 3);
}

__device__ __forceinline__ void mma16816(float& d0, float& d1, float& d2, float& d3,
                                         unsigned a0, unsigned a1, unsigned a2, unsigned a3,
                                         unsigned b0, unsigned b1) {
    asm volatile(
        "mma.sync.aligned.m16n8k16.row.col.f32.f16.f16.f32 "
        "{%0,%1,%2,%3}, {%4,%5,%6,%7}, {%8,%9}, {%0,%1,%2,%3};"
        : "+f"(d0), "+f"(d1), "+f"(d2), "+f"(d3)
        : "r"(a0), "r"(a1), "r"(a2), "r"(a3), "r"(b0), "r"(b1));
}

__device__ __forceinline__ void ldsm_x4(unsigned& a0, unsigned& a1, unsigned& a2, unsigned& a3,
                                        uint32_t addr) {
    asm volatile("ldmatrix.sync.aligned.m8n8.x4.shared.b16 {%0,%1,%2,%3}, [%4];"
                 : "=r"(a0), "=r"(a1), "=r"(a2), "=r"(a3) : "r"(addr));
}

__device__ __forceinline__ uint32_t smem_u32(const void* p) {
    uint32_t a;
    asm("{ .reg .u64 t; cvta.to.shared.u64 t, %1; cvt.u32.u64 %0, t; }" : "=r"(a) : "l"(p));
    return a;
}

__device__ __forceinline__ void stg_cg_u16(__half* p, __half v) {
    unsigned short s = __half_as_ushort(v);
    asm volatile("st.global.cg.u16 [%0], %1;" :: "l"(p), "h"(s) : "memory");
}

__device__ __forceinline__ float sigm(float x) { return 1.0f / (1.0f + __expf(-x)); }
__device__ __forceinline__ float tanh_a(float x) {
    x = fminf(fmaxf(x, -15.f), 15.f);
    float e = __expf(2.f * x);
    return (e - 1.f) / (e + 1.f);
}
__device__ __forceinline__ float lstm_cell(float zi, float zf, float zg, float zo, float& c) {
    float i = sigm(zi), f = sigm(zf), gg = tanh_a(zg), o = sigm(zo);
    c = fmaf(c, f, i * gg);
    return o * tanh_a(c);
}

// ---------------- prep kernels ----------------
__global__ void prep_x_kernel(const float* __restrict__ x) {
    size_t idx = (size_t)blockIdx.x * 256 + threadIdx.x;
    int k = idx & 255;
    int m = (int)(idx >> 8);
    int t = m >> 7, b = m & 127;
    g_x_h[idx] = __float2half_rn(x[((size_t)b * TT + t) * DIN + k]);
}

__global__ void prep_w_kernel(const float* __restrict__ w_x2h, const float* __restrict__ b_x2h,
                              const float* __restrict__ w_h2h, const float* __restrict__ b_h2h) {
    int idx = blockIdx.x * 256 + threadIdx.x;   // 1,048,576 = 2048*512
    {
        int p = idx >> 9, k = idx & 511;
        g_wh[idx] = __float2half_rn(w_h2h[(size_t)k * G4 + gate_col(p)]);
    }
    if (idx < G4 * DIN) {
        int p = idx >> 8, k = idx & 255;
        g_wx[idx] = __float2half_rn(w_x2h[(size_t)k * G4 + gate_col(p)]);
    }
    if (idx < G4) {
        int gc = gate_col(idx);
        g_gbias[idx] = b_x2h[gc] + b_h2h[gc];
    }
    if (idx < RCTA) g_flags[idx] = 0;
}

// ---------------- fused persistent recurrent kernel ----------------
// R15 h-path/protocol verbatim. NEW: x-projection fused in — per CTA its
// 128-col Wx slice lives in smem (loaded once); x_t tile (16x256) double-
// buffered, prefetched 1 step ahead; the 16-kt x-MMA runs BEFORE the poll,
// filling the wait slack. gemm1 + xg tensor deleted.
#define CH_STRIDE 40
#define CH_SZ     (16 * CH_STRIDE)         // 640 halves per chunk
#define WX_HALVES (128 * 264)
#define XS_HALVES (16 * 264)
#define WX_OFF    0
#define XS_OFF    WX_HALVES                // x_sm: [2][16][264]
#define HS_OFF    (WX_HALVES + 2 * XS_HALVES)
#define REC_SMEM  ((WX_HALVES + 2 * XS_HALVES + 16 * CH_SZ) * 2)   // 104,960 B

__global__ __launch_bounds__(256, 1) void rec_kernel() {
    extern __shared__ __half sm[];
    __half* wx_sm = sm + WX_OFF;           // 128 x 264
    __half* x_sm  = sm + XS_OFF;           // 2 x 16 x 264
    __half* h_sm  = sm + HS_OFF;           // 16 chunks x 16 x 40

    const int tid = threadIdx.x;
    const int j = blockIdx.x;
    const int bg = j >> 4, cg = j & 15;
    const int w = tid >> 5, lane = tid & 31;
    const int g = lane >> 2, tq = lane & 3;
    const int b = tq >> 1;

    // -------- prologue: Wh -> regs, Wx slice -> smem, x_0 -> smem, bias -> regs --------
    unsigned breg[128];
    #pragma unroll
    for (int nt = 0; nt < 2; nt++) {
        const __half* wrow = g_wh + (size_t)(cg * 128 + w * 16 + nt * 8 + g) * DH + 2 * tq;
        #pragma unroll
        for (int kt = 0; kt < 32; kt++) {
            breg[nt * 64 + kt * 2]     = *(const unsigned*)(wrow + kt * 16);
            breg[nt * 64 + kt * 2 + 1] = *(const unsigned*)(wrow + kt * 16 + 8);
        }
    }
    {   // Wx slice: 128 rows x 32 uint4
        const uint4* ws = (const uint4*)(g_wx + (size_t)cg * 128 * DIN);
        #pragma unroll
        for (int ii = 0; ii < 16; ii++) {
            int i = tid + ii * 256;
            *(uint4*)&wx_sm[(i >> 5) * 264 + ((i & 31) << 3)] = ws[i];
        }
    }
    {   // x_0 tile: 16 rows x 32 uint4 -> x_sm[0]
        const uint4* xs = (const uint4*)g_x_h + (size_t)(bg * 16) * 32;
        #pragma unroll
        for (int ii = 0; ii < 2; ii++) {
            int i = tid + ii * 256;
            *(uint4*)&x_sm[(i >> 5) * 264 + ((i & 31) << 3)] = xs[(i >> 5) * 32 + (i & 31)];
        }
    }
    float2 gb0 = *(const float2*)&g_gbias[cg * 128 + w * 16 + 2 * tq];
    float2 gb1 = *(const float2*)&g_gbias[cg * 128 + w * 16 + 8 + 2 * tq];
    __syncthreads();

    const uint32_t hbase  = smem_u32(h_sm);
    const uint32_t xbase  = smem_u32(x_sm);
    const int grp = lane >> 3;
    const uint32_t laneoff_h = (uint32_t)(((grp & 1) * 8 + (lane & 7)) * CH_STRIDE
                                          + (grp >> 1) * 8);
    const uint32_t laneoff_x = (uint32_t)(((grp & 1) * 8 + (lane & 7)) * 264
                                          + (grp >> 1) * 8);

    float c0 = 0.f, c1 = 0.f;

    for (int t = 0; t < TT; t++) {
        // prefetch x_{t+1} tile into regs (2 uint4/thread) — in flight all step
        uint4 xp0, xp1;
        int xi0 = tid, xi1 = tid + 256;
        if (t < TT - 1) {
            const uint4* xs = (const uint4*)g_x_h + (size_t)((t + 1) * BB + bg * 16) * 32;
            xp0 = __ldg(xs + (xi0 >> 5) * 32 + (xi0 & 31));
            xp1 = __ldg(xs + (xi1 >> 5) * 32 + (xi1 & 31));
        }

        float accA[2][4], accB[2][4];
        #pragma unroll
        for (int nt = 0; nt < 2; nt++)
            #pragma unroll
            for (int e = 0; e < 4; e++) { accA[nt][e] = 0.f; accB[nt][e] = 0.f; }

        // -------- x-part MMA (independent of h): runs in the wait slack --------
        {
            const uint32_t xb = xbase + (uint32_t)((t & 1) * XS_HALVES) * 2 + laneoff_x * 2;
            #pragma unroll
            for (int kt = 0; kt < 16; kt++) {
                unsigned a0, a1, a2, a3;
                ldsm_x4(a0, a1, a2, a3, xb + kt * 32);
                const int kx = kt * 16 + 2 * tq;
                #pragma unroll
                for (int nt = 0; nt < 2; nt++) {
                    unsigned b0 = *(const unsigned*)&wx_sm[(w * 16 + nt * 8 + g) * 264 + kx];
                    unsigned b1 = *(const unsigned*)&wx_sm[(w * 16 + nt * 8 + g) * 264 + kx + 8];
                    if (kt & 1)
                        mma16816(accB[nt][0], accB[nt][1], accB[nt][2], accB[nt][3],
                                 a0, a1, a2, a3, b0, b1);
                    else
                        mma16816(accA[nt][0], accA[nt][1], accA[nt][2], accA[nt][3],
                                 a0, a1, a2, a3, b0, b1);
                }
            }
        }

        if (t > 0) {
            // R15 protocol: per-warp poll producers 2w, 2w+1
            if (lane < 2) {
                volatile int* fl = g_flags + bg * 16 + 2 * w + lane;
                while (*fl < t) { }
            }
            __syncwarp();
            asm volatile("membar.gl;" ::: "memory");

            // coalesced chunk loads (2KB/warp)
            const uint4* hsrc = (const uint4*)(g_hbuf[t & 1]);
            #pragma unroll
            for (int ci = 0; ci < 2; ci++) {
                const int c = 2 * w + ci;
                const uint4* cb = hsrc + (size_t)(bg * 16 + c) * 64;
                #pragma unroll
                for (int jj = 0; jj < 2; jj++) {
                    int n = lane + jj * 32;
                    uint4 v = __ldcg(cb + n);
                    *(uint4*)&h_sm[c * CH_SZ + (n >> 2) * CH_STRIDE + (n & 3) * 8] = v;
                }
            }
            __syncthreads();

            // h-part MMA: 32 kt, conflict-free ldmatrix, B in regs, chain split
            #pragma unroll
            for (int kt = 0; kt < 32; kt++) {
                const uint32_t a_addr = hbase
                    + (uint32_t)(((kt >> 1) * CH_SZ + (kt & 1) * 16) * 2) + laneoff_h * 2;
                unsigned a0, a1, a2, a3;
                ldsm_x4(a0, a1, a2, a3, a_addr);
                if (kt & 1) {
                    mma16816(accB[0][0], accB[0][1], accB[0][2], accB[0][3],
                             a0, a1, a2, a3, breg[kt * 2], breg[kt * 2 + 1]);
                    mma16816(accB[1][0], accB[1][1], accB[1][2], accB[1][3],
                             a0, a1, a2, a3, breg[64 + kt * 2], breg[64 + kt * 2 + 1]);
                } else {
                    mma16816(accA[0][0], accA[0][1], accA[0][2], accA[0][3],
                             a0, a1, a2, a3, breg[kt * 2], breg[kt * 2 + 1]);
                    mma16816(accA[1][0], accA[1][1], accA[1][2], accA[1][3],
                             a0, a1, a2, a3, breg[64 + kt * 2], breg[64 + kt * 2 + 1]);
                }
            }
        }

        // combine chains + biases
        float acc[2][4];
        #pragma unroll
        for (int nt = 0; nt < 2; nt++)
            #pragma unroll
            for (int e = 0; e < 4; e++) acc[nt][e] = accA[nt][e] + accB[nt][e];
        acc[0][0] += gb0.x; acc[0][1] += gb0.y; acc[0][2] += gb0.x; acc[0][3] += gb0.y;
        acc[1][0] += gb1.x; acc[1][1] += gb1.y; acc[1][2] += gb1.x; acc[1][3] += gb1.y;

        // gate exchange (pair tq, tq^2)
        float r00 = __shfl_xor_sync(0xffffffffu, acc[0][1 - b], 2);
        float r01 = __shfl_xor_sync(0xffffffffu, acc[0][3 - b], 2);
        float r10 = __shfl_xor_sync(0xffffffffu, acc[1][1 - b], 2);
        float r11 = __shfl_xor_sync(0xffffffffu, acc[1][3 - b], 2);
        float o00 = acc[0][b],     o01 = acc[0][2 + b];
        float o10 = acc[1][b],     o11 = acc[1][2 + b];

        float zi0 = b ? r00 : o00,  zf0 = b ? o00 : r00;
        float zg0 = b ? r10 : o10,  zo0 = b ? o10 : r10;
        float zi1 = b ? r01 : o01,  zf1 = b ? o01 : r01;
        float zg1 = b ? r11 : o11,  zo1 = b ? o11 : r11;

        float h0 = lstm_cell(zi0, zf0, zg0, zo0, c0);
        float h1 = lstm_cell(zi1, zf1, zg1, zo1, c1);

        const int ul = w * 4 + (((tq & 1) << 1) | b);

        if (t < TT - 1) {
            // stage x_{t+1} into the other x_sm buffer (readers gated by the
            // publish __syncthreads below)
            {
                __half* xd = x_sm + ((t + 1) & 1) * XS_HALVES;
                *(uint4*)&xd[(xi0 >> 5) * 264 + ((xi0 & 31) << 3)] = xp0;
                *(uint4*)&xd[(xi1 >> 5) * 264 + ((xi1 & 31) << 3)] = xp1;
            }
            // publish h (chunk-major), R15 protocol
            __half* hd = g_hbuf[(t + 1) & 1] + ((size_t)(bg * 16 + cg) * 16) * 32;
            stg_cg_u16(hd + g * 32 + ul,       __float2half_rn(h0));
            stg_cg_u16(hd + (g + 8) * 32 + ul, __float2half_rn(h1));
            __threadfence();
            __syncthreads();
            if (tid == 0) atomicExch(&g_flags[j], t + 1);
        } else {
            const int U = cg * 32 + ul;
            const int row0 = bg * 16 + g, row1 = row0 + 8;
            g_hlast[(size_t)row0 * DH + U] = h0;
            g_hlast[(size_t)row1 * DH + U] = h1;
        }
    }
}

// ---------------- final FC: 4 independent accumulator chains ----------------
__global__ void fc_kernel(const float* __restrict__ w_fc, const float* __restrict__ b_fc,
                          float* __restrict__ out) {
    __shared__ float hs[DH];
    int bb = blockIdx.x, o = threadIdx.x;
    for (int i = o; i < DH; i += 256) hs[i] = g_hlast[bb * DH + i];
    __syncthreads();
    float a0 = 0.f, a1 = 0.f, a2 = 0.f, a3 = 0.f;
    #pragma unroll 8
    for (int k = 0; k < DH; k += 4) {
        a0 = fmaf(hs[k],     w_fc[(size_t)k * DOUT + o],       a0);
        a1 = fmaf(hs[k + 1], w_fc[(size_t)(k + 1) * DOUT + o], a1);
        a2 = fmaf(hs[k + 2], w_fc[(size_t)(k + 2) * DOUT + o], a2);
        a3 = fmaf(hs[k + 3], w_fc[(size_t)(k + 3) * DOUT + o], a3);
    }
    out[bb * DOUT + o] = (a0 + a1) + (a2 + a3) + b_fc[o];
}

// ---------------- launch ----------------
extern "C" void kernel_launch(void* const* d_in, const int* in_sizes, int n_in,
                              void* d_out, int out_size) {
    (void)in_sizes; (void)n_in; (void)out_size;
    const float* x     = (const float*)d_in[0];
    const float* w_x2h = (const float*)d_in[1];
    const float* b_x2h = (const float*)d_in[2];
    const float* w_h2h = (const float*)d_in[3];
    const float* b_h2h = (const float*)d_in[4];
    const float* w_fc  = (const float*)d_in[5];
    const float* b_fc  = (const float*)d_in[6];
    float* out = (float*)d_out;

    cudaFuncSetAttribute(rec_kernel, cudaFuncAttributeMaxDynamicSharedMemorySize, REC_SMEM);

    prep_x_kernel<<<65536, 256>>>(x);
    prep_w_kernel<<<4096, 256>>>(w_x2h, b_x2h, w_h2h, b_h2h);
    rec_kernel<<<RCTA, 256, REC_SMEM>>>();
    fc_kernel<<<BB, 256>>>(w_fc, b_fc, out);
}